// round 7
// baseline (speedup 1.0000x reference)
#include <cuda_runtime.h>
#include <cuda_bf16.h>
#include <cstdint>

// ---------------------------------------------------------------------------
// GIN GNN, 5 layers, D=300, N=100000 nodes, E=200000 edges.
// GEMMs: warp-level mma.sync bf16 (3-way hi/lo split, fp32 accumulate).
// GEMM1: A-stationary (full-K fp32 agg tile split into smem once, loop n).
// GEMM2: inner n-loop (L2 A reuse) + fused BatchNorm statistics.
// ---------------------------------------------------------------------------

#define DD   300
#define DD4  75
#define NL   5

__device__ __align__(16) float g_h  [100000 * 300];
__device__ __align__(16) float g_agg[100000 * 300];
__device__ __align__(16) float g_h2 [100000 * 300];
__device__ __align__(16) float g_stat[600];
__device__ __align__(16) float g_bnA[300];
__device__ __align__(16) float g_bnB[300];

// h1 activations bf16 hi/lo [N,640]
__device__ __align__(16) __nv_bfloat16 g_h1h [100000 * 640];
__device__ __align__(16) __nv_bfloat16 g_h1l [100000 * 640];

// Prepacked weights: bf16 hi/lo, transposed to [n][k], padded.
// B1: [5][2][640 n][320 k]   B2: [5][2][384 n][640 k]
__device__ __align__(16) __nv_bfloat16 g_B1[5 * 2 * 640 * 320];
__device__ __align__(16) __nv_bfloat16 g_B2[5 * 2 * 384 * 640];

// ---------------------------------------------------------------------------
__device__ __forceinline__ uint32_t smem_u32(const void* p) {
    uint32_t a;
    asm("{ .reg .u64 t; cvta.to.shared.u64 t, %1; cvt.u32.u64 %0, t; }"
        : "=r"(a) : "l"(p));
    return a;
}

#define SWZ(off) ((off) ^ (((off) >> 3) & 0x70))

#define CP_ASYNC16(saddr, gaddr, sz) \
    asm volatile("cp.async.cg.shared.global [%0], [%1], 16, %2;" \
                 :: "r"(saddr), "l"(gaddr), "r"(sz) : "memory")
#define CP_COMMIT() asm volatile("cp.async.commit_group;" ::: "memory")
#define CP_WAIT1()  asm volatile("cp.async.wait_group 1;" ::: "memory")
#define CP_WAIT0()  asm volatile("cp.async.wait_group 0;" ::: "memory")

#define LDMX4(r0, r1, r2, r3, addr) \
    asm volatile("ldmatrix.sync.aligned.m8n8.x4.shared.b16 {%0,%1,%2,%3}, [%4];" \
                 : "=r"(r0), "=r"(r1), "=r"(r2), "=r"(r3) : "r"(addr))

#define MMA16816(c0, c1, c2, c3, a0, a1, a2, a3, b0, b1) \
    asm volatile("mma.sync.aligned.m16n8k16.row.col.f32.bf16.bf16.f32 " \
                 "{%0,%1,%2,%3}, {%4,%5,%6,%7}, {%8,%9}, {%0,%1,%2,%3};" \
                 : "+f"(c0), "+f"(c1), "+f"(c2), "+f"(c3) \
                 : "r"(a0), "r"(a1), "r"(a2), "r"(a3), "r"(b0), "r"(b1))

__device__ __forceinline__ void bf16_split4(float4 v, uint2& hp, uint2& lp) {
    __nv_bfloat16 h0 = __float2bfloat16_rn(v.x);
    __nv_bfloat16 h1 = __float2bfloat16_rn(v.y);
    __nv_bfloat16 h2 = __float2bfloat16_rn(v.z);
    __nv_bfloat16 h3 = __float2bfloat16_rn(v.w);
    hp.x = ((uint32_t)__bfloat16_as_ushort(h1) << 16) | __bfloat16_as_ushort(h0);
    hp.y = ((uint32_t)__bfloat16_as_ushort(h3) << 16) | __bfloat16_as_ushort(h2);
    __nv_bfloat16 l0 = __float2bfloat16_rn(v.x - __bfloat162float(h0));
    __nv_bfloat16 l1 = __float2bfloat16_rn(v.y - __bfloat162float(h1));
    __nv_bfloat16 l2 = __float2bfloat16_rn(v.z - __bfloat162float(h2));
    __nv_bfloat16 l3 = __float2bfloat16_rn(v.w - __bfloat162float(h3));
    lp.x = ((uint32_t)__bfloat16_as_ushort(l1) << 16) | __bfloat16_as_ushort(l0);
    lp.y = ((uint32_t)__bfloat16_as_ushort(l3) << 16) | __bfloat16_as_ushort(l2);
}

// ===========================================================================
// GEMM1: h1 = relu(agg @ W1 + b1), A-stationary.
// A: fp32 agg [M,300] -> split to smem hi/lo, 5 chunks of 128x64 (160 KB).
// B buffers: double-buffered (hi+lo) 2x32 KB at G1_BB.
// Out: bf16 hi/lo (row stride 640), cols >= 600 zeroed.
// ===========================================================================
#define G1_ALO 81920
#define G1_BB  163840
#define DSMEM1 (163840 + 65536 + 1024)

__global__ void __launch_bounds__(256)
k_gemm1(const float* __restrict__ A, const __nv_bfloat16* __restrict__ Bp,
        const float* __restrict__ bias,
        __nv_bfloat16* __restrict__ Ch, __nv_bfloat16* __restrict__ Cl,
        int M)
{
    extern __shared__ char dsm[];
    const uint32_t smb = (smem_u32(dsm) + 1023u) & ~1023u;

    const int tid  = threadIdx.x;
    const int wid  = tid >> 5;
    const int lane = tid & 31;
    const int m0 = blockIdx.x * 128;

    const int am = (wid & 1) * 64;
    const int bn = (wid >> 1) * 32;

    const __nv_bfloat16* Bl_ = Bp + 640 * 320;

    // ---- load + split A: 5 chunks, each 128 rows x 64 cols ----
#pragma unroll
    for (int c = 0; c < 5; c++) {
#pragma unroll
        for (int t = 0; t < 8; t++) {
            int idx = t * 256 + tid;          // 0..2047
            int row = idx >> 4;
            int cg  = idx & 15;
            int gcol = c * 64 + cg * 4;
            float4 v = make_float4(0.f, 0.f, 0.f, 0.f);
            int gr = m0 + row;
            if (gr < M && gcol < 300)
                v = *reinterpret_cast<const float4*>(A + (size_t)gr * 300 + gcol);
            uint2 hp, lp;
            bf16_split4(v, hp, lp);
            uint32_t off = SWZ((uint32_t)(row * 128 + cg * 8));
            asm volatile("st.shared.v2.b32 [%0], {%1, %2};"
                         :: "r"(smb + c * 16384 + off), "r"(hp.x), "r"(hp.y) : "memory");
            asm volatile("st.shared.v2.b32 [%0], {%1, %2};"
                         :: "r"(smb + G1_ALO + c * 16384 + off), "r"(lp.x), "r"(lp.y) : "memory");
        }
    }
    __syncthreads();

    auto load_B = [&](int nt, int c) {
        const uint32_t base = smb + G1_BB + (c & 1) * 32768;
        const int k0 = c << 6;
        const int n0 = nt * 128;
#pragma unroll
        for (int t = 0; t < 4; t++) {
            int idx = t * 256 + tid;          // 0..1023
            int row = idx >> 3;
            int c16 = idx & 7;
            uint32_t soff = SWZ((uint32_t)(row * 128 + c16 * 16));
            const char* gh = (const char*)(Bp  + (size_t)(n0 + row) * 320 + k0 + c16 * 8);
            const char* gl = (const char*)(Bl_ + (size_t)(n0 + row) * 320 + k0 + c16 * 8);
            CP_ASYNC16(base + soff, gh, 16u);
            CP_ASYNC16(base + 16384 + soff, gl, 16u);
        }
    };

    const int grp = lane >> 3;
    const int rim = lane & 7;
    const int radd = (grp & 1) * 8;
    const int cadd = (grp >> 1) * 16;
    const int qr = lane >> 2;
    const int qp = (lane & 3) * 2;

    for (int nt = 0; nt < 5; nt++) {
        float acc[4][4][4];
#pragma unroll
        for (int i = 0; i < 4; i++)
#pragma unroll
            for (int j = 0; j < 4; j++)
#pragma unroll
                for (int q = 0; q < 4; q++) acc[i][j][q] = 0.0f;

        load_B(nt, 0);
        CP_COMMIT();

        for (int c = 0; c < 5; c++) {
            if (c + 1 < 5) { load_B(nt, c + 1); CP_COMMIT(); CP_WAIT1(); }
            else           { CP_WAIT0(); }
            __syncthreads();

            const uint32_t ah = smb + c * 16384;
            const uint32_t al = smb + G1_ALO + c * 16384;
            const uint32_t bb = smb + G1_BB + (c & 1) * 32768;
#pragma unroll
            for (int seg = 0; seg < 3; seg++) {
                const uint32_t abase = (seg == 1) ? al : ah;
                const uint32_t bbase = bb + ((seg == 2) ? 16384 : 0);
#pragma unroll
                for (int k16 = 0; k16 < 4; k16++) {
                    const int kb = k16 * 32;
                    uint32_t a[4][4];
#pragma unroll
                    for (int i = 0; i < 4; i++) {
                        uint32_t off = (uint32_t)((am + i * 16 + radd + rim) * 128 + kb + cadd);
                        LDMX4(a[i][0], a[i][1], a[i][2], a[i][3], abase + SWZ(off));
                    }
                    uint32_t b[4][2];
#pragma unroll
                    for (int j = 0; j < 2; j++) {
                        uint32_t r0, r1, r2, r3;
                        uint32_t off = (uint32_t)((bn + j * 16 + radd + rim) * 128 + kb + cadd);
                        LDMX4(r0, r1, r2, r3, bbase + SWZ(off));
                        b[j * 2 + 0][0] = r0; b[j * 2 + 0][1] = r2;
                        b[j * 2 + 1][0] = r1; b[j * 2 + 1][1] = r3;
                    }
#pragma unroll
                    for (int i = 0; i < 4; i++)
#pragma unroll
                        for (int jj = 0; jj < 4; jj++)
                            MMA16816(acc[i][jj][0], acc[i][jj][1], acc[i][jj][2], acc[i][jj][3],
                                     a[i][0], a[i][1], a[i][2], a[i][3],
                                     b[jj][0], b[jj][1]);
                }
            }
            __syncthreads();
        }

        // epilogue: bias + relu, write bf16 hi/lo, zero padding cols >= 600
        const int n0 = nt * 128;
#pragma unroll
        for (int i = 0; i < 4; i++) {
            int r0 = m0 + am + i * 16 + qr;
            int r1 = r0 + 8;
#pragma unroll
            for (int jj = 0; jj < 4; jj++) {
                int col = n0 + bn + jj * 8 + qp;
                float bx = (col < 600) ? bias[col] : 0.0f;
                float by = (col + 1 < 600) ? bias[col + 1] : 0.0f;
                float x0 = fmaxf(acc[i][jj][0] + bx, 0.f);
                float y0 = fmaxf(acc[i][jj][1] + by, 0.f);
                float x1 = fmaxf(acc[i][jj][2] + bx, 0.f);
                float y1 = fmaxf(acc[i][jj][3] + by, 0.f);
                if (col >= 600) { x0 = y0 = x1 = y1 = 0.f; }
                __nv_bfloat16 hx0 = __float2bfloat16_rn(x0);
                __nv_bfloat16 hy0 = __float2bfloat16_rn(y0);
                __nv_bfloat16 hx1 = __float2bfloat16_rn(x1);
                __nv_bfloat16 hy1 = __float2bfloat16_rn(y1);
                uint32_t hp0 = ((uint32_t)__bfloat16_as_ushort(hy0) << 16) | __bfloat16_as_ushort(hx0);
                uint32_t hp1 = ((uint32_t)__bfloat16_as_ushort(hy1) << 16) | __bfloat16_as_ushort(hx1);
                __nv_bfloat16 lx0 = __float2bfloat16_rn(x0 - __bfloat162float(hx0));
                __nv_bfloat16 ly0 = __float2bfloat16_rn(y0 - __bfloat162float(hy0));
                __nv_bfloat16 lx1 = __float2bfloat16_rn(x1 - __bfloat162float(hx1));
                __nv_bfloat16 ly1 = __float2bfloat16_rn(y1 - __bfloat162float(hy1));
                uint32_t lp0 = ((uint32_t)__bfloat16_as_ushort(ly0) << 16) | __bfloat16_as_ushort(lx0);
                uint32_t lp1 = ((uint32_t)__bfloat16_as_ushort(ly1) << 16) | __bfloat16_as_ushort(lx1);
                if (r0 < M) {
                    *(uint32_t*)((char*)Ch + ((size_t)r0 * 640 + col) * 2) = hp0;
                    *(uint32_t*)((char*)Cl + ((size_t)r0 * 640 + col) * 2) = lp0;
                }
                if (r1 < M) {
                    *(uint32_t*)((char*)Ch + ((size_t)r1 * 640 + col) * 2) = hp1;
                    *(uint32_t*)((char*)Cl + ((size_t)r1 * 640 + col) * 2) = lp1;
                }
            }
        }
    }
}

// ===========================================================================
// GEMM2: h2 = h1 @ W2 + b2, inner n-loop (3 tiles), fused BN stats.
// A: bf16 hi/lo [M,640] via cp.async. K chunks of 64 double buffered.
// ===========================================================================
#define A_HI 0
#define A_LO 16384
#define B_HI 32768
#define B_LO 49152
#define BUF_SZ 65536
#define DSMEM2 (2 * BUF_SZ + 1024)

__global__ void __launch_bounds__(256)
k_gemm2(const __nv_bfloat16* __restrict__ Ah,
        const __nv_bfloat16* __restrict__ Al,
        const __nv_bfloat16* __restrict__ Bp,
        const float* __restrict__ bias,
        float* __restrict__ Cf, int M)
{
    extern __shared__ char dsm[];
    const uint32_t smb = (smem_u32(dsm) + 1023u) & ~1023u;

    const int tid  = threadIdx.x;
    const int wid  = tid >> 5;
    const int lane = tid & 31;
    const int m0 = blockIdx.x * 128;

    const int am = (wid & 1) * 64;
    const int bn = (wid >> 1) * 32;

    const __nv_bfloat16* Bl_ = Bp + (size_t)384 * 640;

    auto load_chunk = [&](int n0, int c) {
        const uint32_t base = smb + (c & 1) * BUF_SZ;
        const int k0 = c << 6;
#pragma unroll
        for (int t = 0; t < 4; t++) {
            int idx = t * 256 + tid;
            int row = idx >> 3;
            int c16 = idx & 7;
            uint32_t soff = SWZ((uint32_t)(row * 128 + c16 * 16));
            int gr = m0 + row;
            uint32_t asz = (gr < M) ? 16u : 0u;
            const char* ga = (const char*)(Ah + (size_t)gr * 640 + k0 + c16 * 8);
            const char* gl = (const char*)(Al + (size_t)gr * 640 + k0 + c16 * 8);
            CP_ASYNC16(base + A_HI + soff, ga, asz);
            CP_ASYNC16(base + A_LO + soff, gl, asz);
            const char* gbh = (const char*)(Bp  + (size_t)(n0 + row) * 640 + k0 + c16 * 8);
            const char* gbl = (const char*)(Bl_ + (size_t)(n0 + row) * 640 + k0 + c16 * 8);
            CP_ASYNC16(base + B_HI + soff, gbh, 16u);
            CP_ASYNC16(base + B_LO + soff, gbl, 16u);
        }
    };

    const int grp = lane >> 3;
    const int rim = lane & 7;
    const int radd = (grp & 1) * 8;
    const int cadd = (grp >> 1) * 16;
    const int qr = lane >> 2;
    const int qp = (lane & 3) * 2;

    for (int nt = 0; nt < 3; nt++) {
        const int n0 = nt * 128;
        float acc[4][4][4];
#pragma unroll
        for (int i = 0; i < 4; i++)
#pragma unroll
            for (int j = 0; j < 4; j++)
#pragma unroll
                for (int q = 0; q < 4; q++) acc[i][j][q] = 0.0f;

        load_chunk(n0, 0);
        CP_COMMIT();

        for (int c = 0; c < 10; c++) {
            if (c + 1 < 10) { load_chunk(n0, c + 1); CP_COMMIT(); CP_WAIT1(); }
            else            { CP_WAIT0(); }
            __syncthreads();

            const uint32_t base = smb + (c & 1) * BUF_SZ;
#pragma unroll
            for (int seg = 0; seg < 3; seg++) {
                const uint32_t abase = base + (seg == 1 ? A_LO : A_HI);
                const uint32_t bbase = base + (seg == 2 ? B_LO : B_HI);
#pragma unroll
                for (int k16 = 0; k16 < 4; k16++) {
                    const int kb = k16 * 32;
                    uint32_t a[4][4];
#pragma unroll
                    for (int i = 0; i < 4; i++) {
                        uint32_t off = (uint32_t)((am + i * 16 + radd + rim) * 128 + kb + cadd);
                        LDMX4(a[i][0], a[i][1], a[i][2], a[i][3], abase + SWZ(off));
                    }
                    uint32_t b[4][2];
#pragma unroll
                    for (int j = 0; j < 2; j++) {
                        uint32_t r0, r1, r2, r3;
                        uint32_t off = (uint32_t)((bn + j * 16 + radd + rim) * 128 + kb + cadd);
                        LDMX4(r0, r1, r2, r3, bbase + SWZ(off));
                        b[j * 2 + 0][0] = r0; b[j * 2 + 0][1] = r2;
                        b[j * 2 + 1][0] = r1; b[j * 2 + 1][1] = r3;
                    }
#pragma unroll
                    for (int i = 0; i < 4; i++)
#pragma unroll
                        for (int jj = 0; jj < 4; jj++)
                            MMA16816(acc[i][jj][0], acc[i][jj][1], acc[i][jj][2], acc[i][jj][3],
                                     a[i][0], a[i][1], a[i][2], a[i][3],
                                     b[jj][0], b[jj][1]);
                }
            }
            __syncthreads();
        }

        // ---- epilogue: bias, store fp32, accumulate BN stats ----
        float sx[4], qx[4], sy[4], qy[4];
#pragma unroll
        for (int jj = 0; jj < 4; jj++) { sx[jj] = qx[jj] = sy[jj] = qy[jj] = 0.f; }

#pragma unroll
        for (int i = 0; i < 4; i++) {
            int r0 = m0 + am + i * 16 + qr;
            int r1 = r0 + 8;
#pragma unroll
            for (int jj = 0; jj < 4; jj++) {
                int col = n0 + bn + jj * 8 + qp;
                float bx = (col < 300) ? bias[col] : 0.0f;
                float by = (col + 1 < 300) ? bias[col + 1] : 0.0f;
                float x0 = acc[i][jj][0] + bx, y0 = acc[i][jj][1] + by;
                float x1 = acc[i][jj][2] + bx, y1 = acc[i][jj][3] + by;
                if (r0 < M) {
                    if (col < 300)
                        *(float2*)(Cf + (size_t)r0 * 300 + col) = make_float2(x0, y0);
                    sx[jj] += x0; qx[jj] += x0 * x0;
                    sy[jj] += y0; qy[jj] += y0 * y0;
                }
                if (r1 < M) {
                    if (col < 300)
                        *(float2*)(Cf + (size_t)r1 * 300 + col) = make_float2(x1, y1);
                    sx[jj] += x1; qx[jj] += x1 * x1;
                    sy[jj] += y1; qy[jj] += y1 * y1;
                }
            }
        }
        // reduce over the 8 row-lanes (qr), lanes differing in bits 2..4
#pragma unroll
        for (int jj = 0; jj < 4; jj++) {
#pragma unroll
            for (int mask = 4; mask < 32; mask <<= 1) {
                sx[jj] += __shfl_xor_sync(0xffffffffu, sx[jj], mask);
                qx[jj] += __shfl_xor_sync(0xffffffffu, qx[jj], mask);
                sy[jj] += __shfl_xor_sync(0xffffffffu, sy[jj], mask);
                qy[jj] += __shfl_xor_sync(0xffffffffu, qy[jj], mask);
            }
            if (lane < 4) {
                int col = n0 + bn + jj * 8 + (lane & 3) * 2;
                if (col < 300) {
                    atomicAdd(&g_stat[col], sx[jj]);
                    atomicAdd(&g_stat[DD + col], qx[jj]);
                    atomicAdd(&g_stat[col + 1], sy[jj]);
                    atomicAdd(&g_stat[DD + col + 1], qy[jj]);
                }
            }
        }
    }
}

// ---------------------------------------------------------------------------
// Weight prepack
// ---------------------------------------------------------------------------
__global__ void k_pack1(const float* __restrict__ w1)
{
    int idx = blockIdx.x * 256 + threadIdx.x;
    if (idx >= 5 * 640 * 320) return;
    int k = idx % 320;
    int n = (idx / 320) % 640;
    int l = idx / (320 * 640);
    float v = (n < 600 && k < 300)
        ? w1[(size_t)l * 300 * 600 + (size_t)k * 600 + n] : 0.f;
    __nv_bfloat16 h = __float2bfloat16_rn(v);
    __nv_bfloat16 lo = __float2bfloat16_rn(v - __bfloat162float(h));
    g_B1[((size_t)(l * 2 + 0) * 640 + n) * 320 + k] = h;
    g_B1[((size_t)(l * 2 + 1) * 640 + n) * 320 + k] = lo;
}

__global__ void k_pack2(const float* __restrict__ w2)
{
    int idx = blockIdx.x * 256 + threadIdx.x;
    if (idx >= 5 * 384 * 640) return;
    int k = idx % 640;
    int n = (idx / 640) % 384;
    int l = idx / (640 * 384);
    float v = (n < 300 && k < 600)
        ? w2[(size_t)l * 600 * 300 + (size_t)k * 300 + n] : 0.f;
    __nv_bfloat16 h = __float2bfloat16_rn(v);
    __nv_bfloat16 lo = __float2bfloat16_rn(v - __bfloat162float(h));
    g_B2[((size_t)(l * 2 + 0) * 384 + n) * 640 + k] = h;
    g_B2[((size_t)(l * 2 + 1) * 384 + n) * 640 + k] = lo;
}

// ---------------------------------------------------------------------------
// Embedding + layer-0 agg init
// ---------------------------------------------------------------------------
__global__ void k_embed_init(const int* __restrict__ x,
                             const float4* __restrict__ e1,
                             const float4* __restrict__ e2,
                             const float4* __restrict__ c1,
                             const float4* __restrict__ c2,
                             int n)
{
    int idx = blockIdx.x * blockDim.x + threadIdx.x;
    if (idx >= n * DD4) return;
    int i = idx / DD4;
    int j = idx - i * DD4;
    int a0 = x[2 * i];
    int a1 = x[2 * i + 1];
    float4 v1 = e1[a0 * DD4 + j];
    float4 v2 = e2[a1 * DD4 + j];
    float4 h = make_float4(v1.x + v2.x, v1.y + v2.y, v1.z + v2.z, v1.w + v2.w);
    reinterpret_cast<float4*>(g_h)[idx] = h;
    float4 cc1 = c1[j];
    float4 cc2 = c2[j];
    reinterpret_cast<float4*>(g_agg)[idx] =
        make_float4(h.x + cc1.x + cc2.x, h.y + cc1.y + cc2.y,
                    h.z + cc1.z + cc2.z, h.w + cc1.w + cc2.w);
}

// ---------------------------------------------------------------------------
// Edge scatter
// ---------------------------------------------------------------------------
__global__ void k_scatter(const int* __restrict__ ei,
                          const int* __restrict__ ea,
                          const float* __restrict__ ee1,
                          const float* __restrict__ ee2,
                          int E)
{
    int gw   = (blockIdx.x * blockDim.x + threadIdx.x) >> 5;
    int lane = threadIdx.x & 31;
    if (gw >= E) return;
    int src = ei[gw];
    int dst = ei[E + gw];
    int a0  = ea[2 * gw];
    int a1  = ea[2 * gw + 1];
    const float4* hs = reinterpret_cast<const float4*>(g_h) + (size_t)src * DD4;
    const float4* t1 = reinterpret_cast<const float4*>(ee1) + a0 * DD4;
    const float4* t2 = reinterpret_cast<const float4*>(ee2) + a1 * DD4;
    float4*       ag = reinterpret_cast<float4*>(g_agg) + (size_t)dst * DD4;
    for (int i = lane; i < DD4; i += 32) {
        float4 v = hs[i];
        float4 w1 = t1[i];
        float4 w2 = t2[i];
        float4 m = make_float4(v.x + w1.x + w2.x, v.y + w1.y + w2.y,
                               v.z + w1.z + w2.z, v.w + w1.w + w2.w);
        asm volatile("red.global.add.v4.f32 [%0], {%1,%2,%3,%4};"
                     :: "l"(ag + i), "f"(m.x), "f"(m.y), "f"(m.z), "f"(m.w)
                     : "memory");
    }
}

// ---------------------------------------------------------------------------
// BatchNorm finalize + apply
// ---------------------------------------------------------------------------
__global__ void k_zero600()
{
    int i = threadIdx.x;
    if (i < 600) g_stat[i] = 0.0f;
}

__global__ void k_bnfin(const float* __restrict__ gamma,
                        const float* __restrict__ beta, float invn)
{
    int c = threadIdx.x;
    if (c >= DD) return;
    float mean = g_stat[c] * invn;
    float var  = g_stat[DD + c] * invn - mean * mean;
    float a = gamma[c] * rsqrtf(var + 1e-5f);
    g_bnA[c] = a;
    g_bnB[c] = beta[c] - mean * a;
}

__global__ void k_bnapply(float4* __restrict__ outH,
                          float4* __restrict__ outAgg,
                          const float4* __restrict__ c1,
                          const float4* __restrict__ c2,
                          int n, int doRelu)
{
    int idx = blockIdx.x * blockDim.x + threadIdx.x;
    if (idx >= n * DD4) return;
    int j = idx % DD4;
    float4 v = reinterpret_cast<const float4*>(g_h2)[idx];
    float4 A = reinterpret_cast<const float4*>(g_bnA)[j];
    float4 B = reinterpret_cast<const float4*>(g_bnB)[j];
    float4 o = make_float4(fmaf(A.x, v.x, B.x), fmaf(A.y, v.y, B.y),
                           fmaf(A.z, v.z, B.z), fmaf(A.w, v.w, B.w));
    if (doRelu) {
        o.x = fmaxf(o.x, 0.f); o.y = fmaxf(o.y, 0.f);
        o.z = fmaxf(o.z, 0.f); o.w = fmaxf(o.w, 0.f);
    }
    outH[idx] = o;
    if (outAgg != nullptr) {
        float4 cc1 = c1[j];
        float4 cc2 = c2[j];
        outAgg[idx] = make_float4(o.x + cc1.x + cc2.x, o.y + cc1.y + cc2.y,
                                  o.z + cc1.z + cc2.z, o.w + cc1.w + cc2.w);
    }
}

// ---------------------------------------------------------------------------
// Host launcher
// ---------------------------------------------------------------------------
extern "C" void kernel_launch(void* const* d_in, const int* in_sizes, int n_in,
                              void* d_out, int out_size)
{
    const int*   x     = (const int*)  d_in[0];
    const int*   ei    = (const int*)  d_in[1];
    const int*   ea    = (const int*)  d_in[2];
    const float* xe1   = (const float*)d_in[3];
    const float* xe2   = (const float*)d_in[4];
    const float* ee1   = (const float*)d_in[5];
    const float* ee2   = (const float*)d_in[6];
    const float* w1    = (const float*)d_in[7];
    const float* b1    = (const float*)d_in[8];
    const float* w2    = (const float*)d_in[9];
    const float* b2    = (const float*)d_in[10];
    const float* gamma = (const float*)d_in[11];
    const float* beta  = (const float*)d_in[12];

    const int N = in_sizes[0] / 2;
    const int E = in_sizes[1] / 2;

    float *h, *agg, *h2;
    __nv_bfloat16 *B1, *B2, *h1h, *h1l;
    cudaGetSymbolAddress((void**)&h,    g_h);
    cudaGetSymbolAddress((void**)&agg,  g_agg);
    cudaGetSymbolAddress((void**)&h2,   g_h2);
    cudaGetSymbolAddress((void**)&B1,   g_B1);
    cudaGetSymbolAddress((void**)&B2,   g_B2);
    cudaGetSymbolAddress((void**)&h1h,  g_h1h);
    cudaGetSymbolAddress((void**)&h1l,  g_h1l);

    static bool attrDone = false;
    if (!attrDone) {
        cudaFuncSetAttribute(k_gemm1,
                             cudaFuncAttributeMaxDynamicSharedMemorySize, DSMEM1);
        cudaFuncSetAttribute(k_gemm2,
                             cudaFuncAttributeMaxDynamicSharedMemorySize, DSMEM2);
        attrDone = true;
    }

    const int ewBlocks = (N * DD4 + 255) / 256;
    const int scBlocks = (E * 32 + 255) / 256;
    const int mtiles = (N + 127) / 128;

    k_pack1<<<(5 * 640 * 320 + 255) / 256, 256>>>(w1);
    k_pack2<<<(5 * 384 * 640 + 255) / 256, 256>>>(w2);

    k_embed_init<<<ewBlocks, 256>>>(
        x, (const float4*)xe1, (const float4*)xe2,
        (const float4*)(ee1 + 4 * DD), (const float4*)(ee2), N);

    for (int l = 0; l < NL; l++) {
        const float* ee1l = ee1 + (size_t)l * 7 * DD;
        const float* ee2l = ee2 + (size_t)l * 3 * DD;

        k_scatter<<<scBlocks, 256>>>(ei, ea, ee1l, ee2l, E);

        k_gemm1<<<mtiles, 256, DSMEM1>>>(
            agg, B1 + (size_t)l * 2 * 640 * 320, b1 + (size_t)l * 600,
            h1h, h1l, N);

        k_zero600<<<1, 640>>>();

        k_gemm2<<<mtiles, 256, DSMEM2>>>(
            h1h, h1l, B2 + (size_t)l * 2 * 384 * 640, b2 + (size_t)l * DD,
            h2, N);

        k_bnfin<<<1, 320>>>(gamma + (size_t)l * DD, beta + (size_t)l * DD,
                            1.0f / (float)N);

        const bool last = (l == NL - 1);
        const float* ce1 = last ? ee1 : (ee1 + (size_t)(l + 1) * 7 * DD + 4 * DD);
        const float* ce2 = last ? ee2 : (ee2 + (size_t)(l + 1) * 3 * DD);
        k_bnapply<<<ewBlocks, 256>>>(
            last ? (float4*)d_out : (float4*)h,
            last ? (float4*)nullptr : (float4*)agg,
            (const float4*)ce1, (const float4*)ce2,
            N, last ? 0 : 1);
    }
}

// round 8
// speedup vs baseline: 1.0020x; 1.0020x over previous
#include <cuda_runtime.h>
#include <cuda_bf16.h>
#include <cstdint>

// ---------------------------------------------------------------------------
// GIN GNN, 5 layers, D=300, N=100000 nodes, E=200000 edges.
// GEMMs: warp-level mma.sync bf16 (3-way hi/lo split, fp32 accumulate).
// GEMM1: A-stationary (full-K fp32 agg tile split into smem once, loop n).
// GEMM2: inner n-loop (L2 A reuse) + fused BatchNorm statistics.
// ---------------------------------------------------------------------------

#define DD   300
#define DD4  75
#define NL   5

__device__ __align__(16) float g_h  [100000 * 300];
__device__ __align__(16) float g_agg[100000 * 300];
__device__ __align__(16) float g_h2 [100000 * 300];
__device__ __align__(16) float g_stat[600];
__device__ __align__(16) float g_bnA[300];
__device__ __align__(16) float g_bnB[300];

// h1 activations bf16 hi/lo [N,640]
__device__ __align__(16) __nv_bfloat16 g_h1h [100000 * 640];
__device__ __align__(16) __nv_bfloat16 g_h1l [100000 * 640];

// Prepacked weights: bf16 hi/lo, transposed to [n][k], padded.
// B1: [5][2][640 n][320 k]   B2: [5][2][384 n][640 k]
__device__ __align__(16) __nv_bfloat16 g_B1[5 * 2 * 640 * 320];
__device__ __align__(16) __nv_bfloat16 g_B2[5 * 2 * 384 * 640];

// ---------------------------------------------------------------------------
__device__ __forceinline__ uint32_t smem_u32(const void* p) {
    uint32_t a;
    asm("{ .reg .u64 t; cvta.to.shared.u64 t, %1; cvt.u32.u64 %0, t; }"
        : "=r"(a) : "l"(p));
    return a;
}

#define SWZ(off) ((off) ^ (((off) >> 3) & 0x70))

#define CP_ASYNC16(saddr, gaddr, sz) \
    asm volatile("cp.async.cg.shared.global [%0], [%1], 16, %2;" \
                 :: "r"(saddr), "l"(gaddr), "r"(sz) : "memory")
#define CP_COMMIT() asm volatile("cp.async.commit_group;" ::: "memory")
#define CP_WAIT1()  asm volatile("cp.async.wait_group 1;" ::: "memory")
#define CP_WAIT0()  asm volatile("cp.async.wait_group 0;" ::: "memory")

#define LDMX4(r0, r1, r2, r3, addr) \
    asm volatile("ldmatrix.sync.aligned.m8n8.x4.shared.b16 {%0,%1,%2,%3}, [%4];" \
                 : "=r"(r0), "=r"(r1), "=r"(r2), "=r"(r3) : "r"(addr))

#define MMA16816(c0, c1, c2, c3, a0, a1, a2, a3, b0, b1) \
    asm volatile("mma.sync.aligned.m16n8k16.row.col.f32.bf16.bf16.f32 " \
                 "{%0,%1,%2,%3}, {%4,%5,%6,%7}, {%8,%9}, {%0,%1,%2,%3};" \
                 : "+f"(c0), "+f"(c1), "+f"(c2), "+f"(c3) \
                 : "r"(a0), "r"(a1), "r"(a2), "r"(a3), "r"(b0), "r"(b1))

__device__ __forceinline__ void bf16_split4(float4 v, uint2& hp, uint2& lp) {
    __nv_bfloat16 h0 = __float2bfloat16_rn(v.x);
    __nv_bfloat16 h1 = __float2bfloat16_rn(v.y);
    __nv_bfloat16 h2 = __float2bfloat16_rn(v.z);
    __nv_bfloat16 h3 = __float2bfloat16_rn(v.w);
    hp.x = ((uint32_t)__bfloat16_as_ushort(h1) << 16) | __bfloat16_as_ushort(h0);
    hp.y = ((uint32_t)__bfloat16_as_ushort(h3) << 16) | __bfloat16_as_ushort(h2);
    __nv_bfloat16 l0 = __float2bfloat16_rn(v.x - __bfloat162float(h0));
    __nv_bfloat16 l1 = __float2bfloat16_rn(v.y - __bfloat162float(h1));
    __nv_bfloat16 l2 = __float2bfloat16_rn(v.z - __bfloat162float(h2));
    __nv_bfloat16 l3 = __float2bfloat16_rn(v.w - __bfloat162float(h3));
    lp.x = ((uint32_t)__bfloat16_as_ushort(l1) << 16) | __bfloat16_as_ushort(l0);
    lp.y = ((uint32_t)__bfloat16_as_ushort(l3) << 16) | __bfloat16_as_ushort(l2);
}

// ===========================================================================
// GEMM1: h1 = relu(agg @ W1 + b1), A-stationary.
// A: fp32 agg [M,300] -> split to smem hi/lo, 5 chunks of 128x64 (160 KB).
// B buffers: double-buffered (hi+lo) 2x32 KB at G1_BB.
// Out: bf16 hi/lo (row stride 640), cols >= 600 zeroed.
// ===========================================================================
#define G1_ALO 81920
#define G1_BB  163840
#define DSMEM1 (163840 + 65536 + 1024)

__global__ void __launch_bounds__(256)
k_gemm1(const float* __restrict__ A, const __nv_bfloat16* __restrict__ Bp,
        const float* __restrict__ bias,
        __nv_bfloat16* __restrict__ Ch, __nv_bfloat16* __restrict__ Cl,
        int M)
{
    extern __shared__ char dsm[];
    const uint32_t smb = (smem_u32(dsm) + 1023u) & ~1023u;

    const int tid  = threadIdx.x;
    const int wid  = tid >> 5;
    const int lane = tid & 31;
    const int m0 = blockIdx.x * 128;

    const int am = (wid & 1) * 64;
    const int bn = (wid >> 1) * 32;

    const __nv_bfloat16* Bl_ = Bp + 640 * 320;

    // ---- load + split A: 5 chunks, each 128 rows x 64 cols ----
#pragma unroll
    for (int c = 0; c < 5; c++) {
#pragma unroll
        for (int t = 0; t < 8; t++) {
            int idx = t * 256 + tid;          // 0..2047
            int row = idx >> 4;
            int cg  = idx & 15;
            int gcol = c * 64 + cg * 4;
            float4 v = make_float4(0.f, 0.f, 0.f, 0.f);
            int gr = m0 + row;
            if (gr < M && gcol < 300)
                v = *reinterpret_cast<const float4*>(A + (size_t)gr * 300 + gcol);
            uint2 hp, lp;
            bf16_split4(v, hp, lp);
            uint32_t off = SWZ((uint32_t)(row * 128 + cg * 8));
            asm volatile("st.shared.v2.b32 [%0], {%1, %2};"
                         :: "r"(smb + c * 16384 + off), "r"(hp.x), "r"(hp.y) : "memory");
            asm volatile("st.shared.v2.b32 [%0], {%1, %2};"
                         :: "r"(smb + G1_ALO + c * 16384 + off), "r"(lp.x), "r"(lp.y) : "memory");
        }
    }
    __syncthreads();

    auto load_B = [&](int nt, int c) {
        const uint32_t base = smb + G1_BB + (c & 1) * 32768;
        const int k0 = c << 6;
        const int n0 = nt * 128;
#pragma unroll
        for (int t = 0; t < 4; t++) {
            int idx = t * 256 + tid;          // 0..1023
            int row = idx >> 3;
            int c16 = idx & 7;
            uint32_t soff = SWZ((uint32_t)(row * 128 + c16 * 16));
            const char* gh = (const char*)(Bp  + (size_t)(n0 + row) * 320 + k0 + c16 * 8);
            const char* gl = (const char*)(Bl_ + (size_t)(n0 + row) * 320 + k0 + c16 * 8);
            CP_ASYNC16(base + soff, gh, 16u);
            CP_ASYNC16(base + 16384 + soff, gl, 16u);
        }
    };

    const int grp = lane >> 3;
    const int rim = lane & 7;
    const int radd = (grp & 1) * 8;
    const int cadd = (grp >> 1) * 16;
    const int qr = lane >> 2;
    const int qp = (lane & 3) * 2;

    for (int nt = 0; nt < 5; nt++) {
        float acc[4][4][4];
#pragma unroll
        for (int i = 0; i < 4; i++)
#pragma unroll
            for (int j = 0; j < 4; j++)
#pragma unroll
                for (int q = 0; q < 4; q++) acc[i][j][q] = 0.0f;

        load_B(nt, 0);
        CP_COMMIT();

        for (int c = 0; c < 5; c++) {
            if (c + 1 < 5) { load_B(nt, c + 1); CP_COMMIT(); CP_WAIT1(); }
            else           { CP_WAIT0(); }
            __syncthreads();

            const uint32_t ah = smb + c * 16384;
            const uint32_t al = smb + G1_ALO + c * 16384;
            const uint32_t bb = smb + G1_BB + (c & 1) * 32768;
#pragma unroll
            for (int seg = 0; seg < 3; seg++) {
                const uint32_t abase = (seg == 1) ? al : ah;
                const uint32_t bbase = bb + ((seg == 2) ? 16384 : 0);
#pragma unroll
                for (int k16 = 0; k16 < 4; k16++) {
                    const int kb = k16 * 32;
                    uint32_t a[4][4];
#pragma unroll
                    for (int i = 0; i < 4; i++) {
                        uint32_t off = (uint32_t)((am + i * 16 + radd + rim) * 128 + kb + cadd);
                        LDMX4(a[i][0], a[i][1], a[i][2], a[i][3], abase + SWZ(off));
                    }
                    uint32_t b[4][2];
#pragma unroll
                    for (int j = 0; j < 2; j++) {
                        uint32_t r0, r1, r2, r3;
                        uint32_t off = (uint32_t)((bn + j * 16 + radd + rim) * 128 + kb + cadd);
                        LDMX4(r0, r1, r2, r3, bbase + SWZ(off));
                        b[j * 2 + 0][0] = r0; b[j * 2 + 0][1] = r2;
                        b[j * 2 + 1][0] = r1; b[j * 2 + 1][1] = r3;
                    }
#pragma unroll
                    for (int i = 0; i < 4; i++)
#pragma unroll
                        for (int jj = 0; jj < 4; jj++)
                            MMA16816(acc[i][jj][0], acc[i][jj][1], acc[i][jj][2], acc[i][jj][3],
                                     a[i][0], a[i][1], a[i][2], a[i][3],
                                     b[jj][0], b[jj][1]);
                }
            }
            __syncthreads();
        }

        // epilogue: bias + relu, write bf16 hi/lo, zero padding cols >= 600
        const int n0 = nt * 128;
#pragma unroll
        for (int i = 0; i < 4; i++) {
            int r0 = m0 + am + i * 16 + qr;
            int r1 = r0 + 8;
#pragma unroll
            for (int jj = 0; jj < 4; jj++) {
                int col = n0 + bn + jj * 8 + qp;
                float bx = (col < 600) ? bias[col] : 0.0f;
                float by = (col + 1 < 600) ? bias[col + 1] : 0.0f;
                float x0 = fmaxf(acc[i][jj][0] + bx, 0.f);
                float y0 = fmaxf(acc[i][jj][1] + by, 0.f);
                float x1 = fmaxf(acc[i][jj][2] + bx, 0.f);
                float y1 = fmaxf(acc[i][jj][3] + by, 0.f);
                if (col >= 600) { x0 = y0 = x1 = y1 = 0.f; }
                __nv_bfloat16 hx0 = __float2bfloat16_rn(x0);
                __nv_bfloat16 hy0 = __float2bfloat16_rn(y0);
                __nv_bfloat16 hx1 = __float2bfloat16_rn(x1);
                __nv_bfloat16 hy1 = __float2bfloat16_rn(y1);
                uint32_t hp0 = ((uint32_t)__bfloat16_as_ushort(hy0) << 16) | __bfloat16_as_ushort(hx0);
                uint32_t hp1 = ((uint32_t)__bfloat16_as_ushort(hy1) << 16) | __bfloat16_as_ushort(hx1);
                __nv_bfloat16 lx0 = __float2bfloat16_rn(x0 - __bfloat162float(hx0));
                __nv_bfloat16 ly0 = __float2bfloat16_rn(y0 - __bfloat162float(hy0));
                __nv_bfloat16 lx1 = __float2bfloat16_rn(x1 - __bfloat162float(hx1));
                __nv_bfloat16 ly1 = __float2bfloat16_rn(y1 - __bfloat162float(hy1));
                uint32_t lp0 = ((uint32_t)__bfloat16_as_ushort(ly0) << 16) | __bfloat16_as_ushort(lx0);
                uint32_t lp1 = ((uint32_t)__bfloat16_as_ushort(ly1) << 16) | __bfloat16_as_ushort(lx1);
                if (r0 < M) {
                    *(uint32_t*)((char*)Ch + ((size_t)r0 * 640 + col) * 2) = hp0;
                    *(uint32_t*)((char*)Cl + ((size_t)r0 * 640 + col) * 2) = lp0;
                }
                if (r1 < M) {
                    *(uint32_t*)((char*)Ch + ((size_t)r1 * 640 + col) * 2) = hp1;
                    *(uint32_t*)((char*)Cl + ((size_t)r1 * 640 + col) * 2) = lp1;
                }
            }
        }
    }
}

// ===========================================================================
// GEMM2: h2 = h1 @ W2 + b2, inner n-loop (3 tiles), fused BN stats.
// A: bf16 hi/lo [M,640] via cp.async. K chunks of 64 double buffered.
// ===========================================================================
#define A_HI 0
#define A_LO 16384
#define B_HI 32768
#define B_LO 49152
#define BUF_SZ 65536
#define DSMEM2 (2 * BUF_SZ + 1024)

__global__ void __launch_bounds__(256)
k_gemm2(const __nv_bfloat16* __restrict__ Ah,
        const __nv_bfloat16* __restrict__ Al,
        const __nv_bfloat16* __restrict__ Bp,
        const float* __restrict__ bias,
        float* __restrict__ Cf, int M)
{
    extern __shared__ char dsm[];
    const uint32_t smb = (smem_u32(dsm) + 1023u) & ~1023u;

    const int tid  = threadIdx.x;
    const int wid  = tid >> 5;
    const int lane = tid & 31;
    const int m0 = blockIdx.x * 128;

    const int am = (wid & 1) * 64;
    const int bn = (wid >> 1) * 32;

    const __nv_bfloat16* Bl_ = Bp + (size_t)384 * 640;

    auto load_chunk = [&](int n0, int c) {
        const uint32_t base = smb + (c & 1) * BUF_SZ;
        const int k0 = c << 6;
#pragma unroll
        for (int t = 0; t < 4; t++) {
            int idx = t * 256 + tid;
            int row = idx >> 3;
            int c16 = idx & 7;
            uint32_t soff = SWZ((uint32_t)(row * 128 + c16 * 16));
            int gr = m0 + row;
            uint32_t asz = (gr < M) ? 16u : 0u;
            const char* ga = (const char*)(Ah + (size_t)gr * 640 + k0 + c16 * 8);
            const char* gl = (const char*)(Al + (size_t)gr * 640 + k0 + c16 * 8);
            CP_ASYNC16(base + A_HI + soff, ga, asz);
            CP_ASYNC16(base + A_LO + soff, gl, asz);
            const char* gbh = (const char*)(Bp  + (size_t)(n0 + row) * 640 + k0 + c16 * 8);
            const char* gbl = (const char*)(Bl_ + (size_t)(n0 + row) * 640 + k0 + c16 * 8);
            CP_ASYNC16(base + B_HI + soff, gbh, 16u);
            CP_ASYNC16(base + B_LO + soff, gbl, 16u);
        }
    };

    const int grp = lane >> 3;
    const int rim = lane & 7;
    const int radd = (grp & 1) * 8;
    const int cadd = (grp >> 1) * 16;
    const int qr = lane >> 2;
    const int qp = (lane & 3) * 2;

    for (int nt = 0; nt < 3; nt++) {
        const int n0 = nt * 128;
        float acc[4][4][4];
#pragma unroll
        for (int i = 0; i < 4; i++)
#pragma unroll
            for (int j = 0; j < 4; j++)
#pragma unroll
                for (int q = 0; q < 4; q++) acc[i][j][q] = 0.0f;

        load_chunk(n0, 0);
        CP_COMMIT();

        for (int c = 0; c < 10; c++) {
            if (c + 1 < 10) { load_chunk(n0, c + 1); CP_COMMIT(); CP_WAIT1(); }
            else            { CP_WAIT0(); }
            __syncthreads();

            const uint32_t base = smb + (c & 1) * BUF_SZ;
#pragma unroll
            for (int seg = 0; seg < 3; seg++) {
                const uint32_t abase = base + (seg == 1 ? A_LO : A_HI);
                const uint32_t bbase = base + (seg == 2 ? B_LO : B_HI);
#pragma unroll
                for (int k16 = 0; k16 < 4; k16++) {
                    const int kb = k16 * 32;
                    uint32_t a[4][4];
#pragma unroll
                    for (int i = 0; i < 4; i++) {
                        uint32_t off = (uint32_t)((am + i * 16 + radd + rim) * 128 + kb + cadd);
                        LDMX4(a[i][0], a[i][1], a[i][2], a[i][3], abase + SWZ(off));
                    }
                    uint32_t b[4][2];
#pragma unroll
                    for (int j = 0; j < 2; j++) {
                        uint32_t r0, r1, r2, r3;
                        uint32_t off = (uint32_t)((bn + j * 16 + radd + rim) * 128 + kb + cadd);
                        LDMX4(r0, r1, r2, r3, bbase + SWZ(off));
                        b[j * 2 + 0][0] = r0; b[j * 2 + 0][1] = r2;
                        b[j * 2 + 1][0] = r1; b[j * 2 + 1][1] = r3;
                    }
#pragma unroll
                    for (int i = 0; i < 4; i++)
#pragma unroll
                        for (int jj = 0; jj < 4; jj++)
                            MMA16816(acc[i][jj][0], acc[i][jj][1], acc[i][jj][2], acc[i][jj][3],
                                     a[i][0], a[i][1], a[i][2], a[i][3],
                                     b[jj][0], b[jj][1]);
                }
            }
            __syncthreads();
        }

        // ---- epilogue: bias, store fp32, accumulate BN stats ----
        float sx[4], qx[4], sy[4], qy[4];
#pragma unroll
        for (int jj = 0; jj < 4; jj++) { sx[jj] = qx[jj] = sy[jj] = qy[jj] = 0.f; }

#pragma unroll
        for (int i = 0; i < 4; i++) {
            int r0 = m0 + am + i * 16 + qr;
            int r1 = r0 + 8;
#pragma unroll
            for (int jj = 0; jj < 4; jj++) {
                int col = n0 + bn + jj * 8 + qp;
                float bx = (col < 300) ? bias[col] : 0.0f;
                float by = (col + 1 < 300) ? bias[col + 1] : 0.0f;
                float x0 = acc[i][jj][0] + bx, y0 = acc[i][jj][1] + by;
                float x1 = acc[i][jj][2] + bx, y1 = acc[i][jj][3] + by;
                if (r0 < M) {
                    if (col < 300)
                        *(float2*)(Cf + (size_t)r0 * 300 + col) = make_float2(x0, y0);
                    sx[jj] += x0; qx[jj] += x0 * x0;
                    sy[jj] += y0; qy[jj] += y0 * y0;
                }
                if (r1 < M) {
                    if (col < 300)
                        *(float2*)(Cf + (size_t)r1 * 300 + col) = make_float2(x1, y1);
                    sx[jj] += x1; qx[jj] += x1 * x1;
                    sy[jj] += y1; qy[jj] += y1 * y1;
                }
            }
        }
        // reduce over the 8 row-lanes (qr), lanes differing in bits 2..4
#pragma unroll
        for (int jj = 0; jj < 4; jj++) {
#pragma unroll
            for (int mask = 4; mask < 32; mask <<= 1) {
                sx[jj] += __shfl_xor_sync(0xffffffffu, sx[jj], mask);
                qx[jj] += __shfl_xor_sync(0xffffffffu, qx[jj], mask);
                sy[jj] += __shfl_xor_sync(0xffffffffu, sy[jj], mask);
                qy[jj] += __shfl_xor_sync(0xffffffffu, qy[jj], mask);
            }
            if (lane < 4) {
                int col = n0 + bn + jj * 8 + (lane & 3) * 2;
                if (col < 300) {
                    atomicAdd(&g_stat[col], sx[jj]);
                    atomicAdd(&g_stat[DD + col], qx[jj]);
                    atomicAdd(&g_stat[col + 1], sy[jj]);
                    atomicAdd(&g_stat[DD + col + 1], qy[jj]);
                }
            }
        }
    }
}

// ---------------------------------------------------------------------------
// Weight prepack
// ---------------------------------------------------------------------------
__global__ void k_pack1(const float* __restrict__ w1)
{
    int idx = blockIdx.x * 256 + threadIdx.x;
    if (idx >= 5 * 640 * 320) return;
    int k = idx % 320;
    int n = (idx / 320) % 640;
    int l = idx / (320 * 640);
    float v = (n < 600 && k < 300)
        ? w1[(size_t)l * 300 * 600 + (size_t)k * 600 + n] : 0.f;
    __nv_bfloat16 h = __float2bfloat16_rn(v);
    __nv_bfloat16 lo = __float2bfloat16_rn(v - __bfloat162float(h));
    g_B1[((size_t)(l * 2 + 0) * 640 + n) * 320 + k] = h;
    g_B1[((size_t)(l * 2 + 1) * 640 + n) * 320 + k] = lo;
}

__global__ void k_pack2(const float* __restrict__ w2)
{
    int idx = blockIdx.x * 256 + threadIdx.x;
    if (idx >= 5 * 384 * 640) return;
    int k = idx % 640;
    int n = (idx / 640) % 384;
    int l = idx / (640 * 384);
    float v = (n < 300 && k < 600)
        ? w2[(size_t)l * 600 * 300 + (size_t)k * 300 + n] : 0.f;
    __nv_bfloat16 h = __float2bfloat16_rn(v);
    __nv_bfloat16 lo = __float2bfloat16_rn(v - __bfloat162float(h));
    g_B2[((size_t)(l * 2 + 0) * 384 + n) * 640 + k] = h;
    g_B2[((size_t)(l * 2 + 1) * 384 + n) * 640 + k] = lo;
}

// ---------------------------------------------------------------------------
// Embedding + layer-0 agg init
// ---------------------------------------------------------------------------
__global__ void k_embed_init(const int* __restrict__ x,
                             const float4* __restrict__ e1,
                             const float4* __restrict__ e2,
                             const float4* __restrict__ c1,
                             const float4* __restrict__ c2,
                             int n)
{
    int idx = blockIdx.x * blockDim.x + threadIdx.x;
    if (idx >= n * DD4) return;
    int i = idx / DD4;
    int j = idx - i * DD4;
    int a0 = x[2 * i];
    int a1 = x[2 * i + 1];
    float4 v1 = e1[a0 * DD4 + j];
    float4 v2 = e2[a1 * DD4 + j];
    float4 h = make_float4(v1.x + v2.x, v1.y + v2.y, v1.z + v2.z, v1.w + v2.w);
    reinterpret_cast<float4*>(g_h)[idx] = h;
    float4 cc1 = c1[j];
    float4 cc2 = c2[j];
    reinterpret_cast<float4*>(g_agg)[idx] =
        make_float4(h.x + cc1.x + cc2.x, h.y + cc1.y + cc2.y,
                    h.z + cc1.z + cc2.z, h.w + cc1.w + cc2.w);
}

// ---------------------------------------------------------------------------
// Edge scatter
// ---------------------------------------------------------------------------
__global__ void k_scatter(const int* __restrict__ ei,
                          const int* __restrict__ ea,
                          const float* __restrict__ ee1,
                          const float* __restrict__ ee2,
                          int E)
{
    int gw   = (blockIdx.x * blockDim.x + threadIdx.x) >> 5;
    int lane = threadIdx.x & 31;
    if (gw >= E) return;
    int src = ei[gw];
    int dst = ei[E + gw];
    int a0  = ea[2 * gw];
    int a1  = ea[2 * gw + 1];
    const float4* hs = reinterpret_cast<const float4*>(g_h) + (size_t)src * DD4;
    const float4* t1 = reinterpret_cast<const float4*>(ee1) + a0 * DD4;
    const float4* t2 = reinterpret_cast<const float4*>(ee2) + a1 * DD4;
    float4*       ag = reinterpret_cast<float4*>(g_agg) + (size_t)dst * DD4;
    for (int i = lane; i < DD4; i += 32) {
        float4 v = hs[i];
        float4 w1 = t1[i];
        float4 w2 = t2[i];
        float4 m = make_float4(v.x + w1.x + w2.x, v.y + w1.y + w2.y,
                               v.z + w1.z + w2.z, v.w + w1.w + w2.w);
        asm volatile("red.global.add.v4.f32 [%0], {%1,%2,%3,%4};"
                     :: "l"(ag + i), "f"(m.x), "f"(m.y), "f"(m.z), "f"(m.w)
                     : "memory");
    }
}

// ---------------------------------------------------------------------------
// BatchNorm finalize + apply
// ---------------------------------------------------------------------------
__global__ void k_zero600()
{
    int i = threadIdx.x;
    if (i < 600) g_stat[i] = 0.0f;
}

__global__ void k_bnfin(const float* __restrict__ gamma,
                        const float* __restrict__ beta, float invn)
{
    int c = threadIdx.x;
    if (c >= DD) return;
    float mean = g_stat[c] * invn;
    float var  = g_stat[DD + c] * invn - mean * mean;
    float a = gamma[c] * rsqrtf(var + 1e-5f);
    g_bnA[c] = a;
    g_bnB[c] = beta[c] - mean * a;
}

__global__ void k_bnapply(float4* __restrict__ outH,
                          float4* __restrict__ outAgg,
                          const float4* __restrict__ c1,
                          const float4* __restrict__ c2,
                          int n, int doRelu)
{
    int idx = blockIdx.x * blockDim.x + threadIdx.x;
    if (idx >= n * DD4) return;
    int j = idx % DD4;
    float4 v = reinterpret_cast<const float4*>(g_h2)[idx];
    float4 A = reinterpret_cast<const float4*>(g_bnA)[j];
    float4 B = reinterpret_cast<const float4*>(g_bnB)[j];
    float4 o = make_float4(fmaf(A.x, v.x, B.x), fmaf(A.y, v.y, B.y),
                           fmaf(A.z, v.z, B.z), fmaf(A.w, v.w, B.w));
    if (doRelu) {
        o.x = fmaxf(o.x, 0.f); o.y = fmaxf(o.y, 0.f);
        o.z = fmaxf(o.z, 0.f); o.w = fmaxf(o.w, 0.f);
    }
    outH[idx] = o;
    if (outAgg != nullptr) {
        float4 cc1 = c1[j];
        float4 cc2 = c2[j];
        outAgg[idx] = make_float4(o.x + cc1.x + cc2.x, o.y + cc1.y + cc2.y,
                                  o.z + cc1.z + cc2.z, o.w + cc1.w + cc2.w);
    }
}

// ---------------------------------------------------------------------------
// Host launcher
// ---------------------------------------------------------------------------
extern "C" void kernel_launch(void* const* d_in, const int* in_sizes, int n_in,
                              void* d_out, int out_size)
{
    const int*   x     = (const int*)  d_in[0];
    const int*   ei    = (const int*)  d_in[1];
    const int*   ea    = (const int*)  d_in[2];
    const float* xe1   = (const float*)d_in[3];
    const float* xe2   = (const float*)d_in[4];
    const float* ee1   = (const float*)d_in[5];
    const float* ee2   = (const float*)d_in[6];
    const float* w1    = (const float*)d_in[7];
    const float* b1    = (const float*)d_in[8];
    const float* w2    = (const float*)d_in[9];
    const float* b2    = (const float*)d_in[10];
    const float* gamma = (const float*)d_in[11];
    const float* beta  = (const float*)d_in[12];

    const int N = in_sizes[0] / 2;
    const int E = in_sizes[1] / 2;

    float *h, *agg, *h2;
    __nv_bfloat16 *B1, *B2, *h1h, *h1l;
    cudaGetSymbolAddress((void**)&h,    g_h);
    cudaGetSymbolAddress((void**)&agg,  g_agg);
    cudaGetSymbolAddress((void**)&h2,   g_h2);
    cudaGetSymbolAddress((void**)&B1,   g_B1);
    cudaGetSymbolAddress((void**)&B2,   g_B2);
    cudaGetSymbolAddress((void**)&h1h,  g_h1h);
    cudaGetSymbolAddress((void**)&h1l,  g_h1l);

    static bool attrDone = false;
    if (!attrDone) {
        cudaFuncSetAttribute(k_gemm1,
                             cudaFuncAttributeMaxDynamicSharedMemorySize, DSMEM1);
        cudaFuncSetAttribute(k_gemm2,
                             cudaFuncAttributeMaxDynamicSharedMemorySize, DSMEM2);
        attrDone = true;
    }

    const int ewBlocks = (N * DD4 + 255) / 256;
    const int scBlocks = (E * 32 + 255) / 256;
    const int mtiles = (N + 127) / 128;

    k_pack1<<<(5 * 640 * 320 + 255) / 256, 256>>>(w1);
    k_pack2<<<(5 * 384 * 640 + 255) / 256, 256>>>(w2);

    k_embed_init<<<ewBlocks, 256>>>(
        x, (const float4*)xe1, (const float4*)xe2,
        (const float4*)(ee1 + 4 * DD), (const float4*)(ee2), N);

    for (int l = 0; l < NL; l++) {
        const float* ee1l = ee1 + (size_t)l * 7 * DD;
        const float* ee2l = ee2 + (size_t)l * 3 * DD;

        k_scatter<<<scBlocks, 256>>>(ei, ea, ee1l, ee2l, E);

        k_gemm1<<<mtiles, 256, DSMEM1>>>(
            agg, B1 + (size_t)l * 2 * 640 * 320, b1 + (size_t)l * 600,
            h1h, h1l, N);

        k_zero600<<<1, 640>>>();

        k_gemm2<<<mtiles, 256, DSMEM2>>>(
            h1h, h1l, B2 + (size_t)l * 2 * 384 * 640, b2 + (size_t)l * DD,
            h2, N);

        k_bnfin<<<1, 320>>>(gamma + (size_t)l * DD, beta + (size_t)l * DD,
                            1.0f / (float)N);

        const bool last = (l == NL - 1);
        const float* ce1 = last ? ee1 : (ee1 + (size_t)(l + 1) * 7 * DD + 4 * DD);
        const float* ce2 = last ? ee2 : (ee2 + (size_t)(l + 1) * 3 * DD);
        k_bnapply<<<ewBlocks, 256>>>(
            last ? (float4*)d_out : (float4*)h,
            last ? (float4*)nullptr : (float4*)agg,
            (const float4*)ce1, (const float4*)ce2,
            N, last ? 0 : 1);
    }
}